// round 10
// baseline (speedup 1.0000x reference)
#include <cuda_runtime.h>
#include <cuda_bf16.h>

// Problem constants: B=32, M=32768, D=128, R=64, W=129
#define RB_B 32
#define RB_M 32768
#define RB_D 128
#define RB_W 129
#define THREADS 256
#define UNROLL 4
#define CHUNK (THREADS * UNROLL)          // 1024 float4 per CTA-iteration = 32 rows
#define NCHUNK ((RB_B * RB_M * (RB_D/4)) / CHUNK)   // 32768 chunks total
#define GRID 1184                          // 148 SMs * 8 CTAs: exactly one wave

// out[b,m,:] = ring[b,m,:] unless off=(m-start[b]) mod M < W:
//   w = weights[b,off]; out = ring*(1-erase[b]*w) + write_gate[b]*w*write_vec[b,:]
//
// HBM-bound copy (512MB R + 512MB W compulsory), at the sustained-BW plateau.
// This version is persistent grid-stride: one wave of CTAs loops over all
// chunks, eliminating 13 wave transitions and keeping a steady per-SM load
// queue (loads of iteration i+1 overlap stores of iteration i).

__global__ __launch_bounds__(THREADS, 8) void ring_update_kernel(
    const float4* __restrict__ ring4,     // B*M*D/4 float4
    const float4* __restrict__ wvec4,     // B*D/4 float4
    const float*  __restrict__ weights,   // B*W
    const float*  __restrict__ erase,     // B
    const float*  __restrict__ wgate,     // B
    const int*    __restrict__ idx,       // B*W
    float4*       __restrict__ out4)
{
    const int D4 = RB_D / 4;  // 32

    for (int chunk = blockIdx.x; chunk < NCHUNK; chunk += GRID) {
        int g = chunk * CHUNK + threadIdx.x;

        float4 cur[UNROLL];
        // Front-batched independent loads: MLP_p1 = 4, streaming (no reuse).
#pragma unroll
        for (int k = 0; k < UNROLL; k++) {
            cur[k] = __ldcs(&ring4[g + k * THREADS]);
        }

        // Chunk (32 rows) lies fully inside one batch (2^20 float4/batch is a
        // multiple of CHUNK): per-batch scalars hoisted, L1-resident.
        int b      = g >> 20;
        int start  = __ldg(&idx[b * RB_W]);
        float e    = __ldg(&erase[b]);
        float gt   = __ldg(&wgate[b]);

#pragma unroll
        for (int k = 0; k < UNROLL; k++) {
            int v   = g + k * THREADS;
            int row = v >> 5;                 // b*M + m
            int m   = row & (RB_M - 1);
            int off = (m - start) & (RB_M - 1);

            if (off < RB_W) {
                int   d4 = v & (D4 - 1);
                float w  = __ldg(&weights[b * RB_W + off]);
                float keep = 1.0f - e * w;
                float add  = gt * w;
                float4 wv = __ldg(&wvec4[b * D4 + d4]);
                cur[k].x = cur[k].x * keep + add * wv.x;
                cur[k].y = cur[k].y * keep + add * wv.y;
                cur[k].z = cur[k].z * keep + add * wv.z;
                cur[k].w = cur[k].w * keep + add * wv.w;
            }
        }

#pragma unroll
        for (int k = 0; k < UNROLL; k++) {
            __stcs(&out4[g + k * THREADS], cur[k]);
        }
    }
}

extern "C" void kernel_launch(void* const* d_in, const int* in_sizes, int n_in,
                              void* d_out, int out_size)
{
    const float4* ring4   = (const float4*)d_in[0];
    const float4* wvec4   = (const float4*)d_in[1];
    const float*  weights = (const float*)d_in[2];
    const float*  erase   = (const float*)d_in[3];
    const float*  wgate   = (const float*)d_in[4];
    const int*    idx     = (const int*)d_in[5];
    float4*       out4    = (float4*)d_out;

    ring_update_kernel<<<GRID, THREADS>>>(ring4, wvec4, weights, erase, wgate, idx, out4);
}

// round 11
// speedup vs baseline: 1.1193x; 1.1193x over previous
#include <cuda_runtime.h>
#include <cuda_bf16.h>

// Problem constants: B=32, M=32768, D=128, R=64, W=129
#define RB_B 32
#define RB_M 32768
#define RB_D 128
#define RB_W 129

// out[b,m,:] = ring[b,m,:] unless off=(m-start[b]) mod M < W:
//   w = weights[b,off]; out = ring*(1-erase[b]*w) + write_gate[b]*w*write_vec[b,:]
//
// HBM-bound copy (512MB R + 512MB W compulsory). Converged configuration
// (best of 5 measured variants, R6): one-shot CTAs, 256 threads, MLP_p1=4
// front-batched LDG.128 with streaming hints, 32 regs -> ~8 CTA/SM.
// Measured: 6.80 TB/s sustained (86% of spec) — at the sm_103a sustained
// HBM ceiling for this pattern; persistent/deeper-MLP/bigger-block variants
// are all neutral or worse.

__global__ __launch_bounds__(256) void ring_update_kernel(
    const float4* __restrict__ ring4,     // B*M*D/4 float4
    const float4* __restrict__ wvec4,     // B*D/4 float4
    const float*  __restrict__ weights,   // B*W
    const float*  __restrict__ erase,     // B
    const float*  __restrict__ wgate,     // B
    const int*    __restrict__ idx,       // B*W
    float4*       __restrict__ out4)
{
    const int D4 = RB_D / 4;  // 32

    // Block covers 4*256 = 1024 consecutive float4s (= 32 full rows),
    // always fully inside one batch (per-batch 2^20 float4 is a multiple).
    int g = blockIdx.x * 1024 + threadIdx.x;

    float4 cur[4];

    // Front-batched independent loads: MLP_p1 = 4, streaming (no reuse).
#pragma unroll
    for (int k = 0; k < 4; k++) {
        cur[k] = __ldcs(&ring4[g + k * 256]);
    }

    // Per-batch scalars: one broadcast load each, L1-resident.
    int b      = g >> 20;                  // (b*M+m)*32+d4 ; M*D4 = 2^20
    int start  = __ldg(&idx[b * RB_W]);
    float e    = __ldg(&erase[b]);
    float gt   = __ldg(&wgate[b]);

#pragma unroll
    for (int k = 0; k < 4; k++) {
        int v   = g + k * 256;
        int row = v >> 5;                  // b*M + m
        int m   = row & (RB_M - 1);
        int off = (m - start) & (RB_M - 1);

        if (off < RB_W) {
            int   d4 = v & (D4 - 1);
            float w  = __ldg(&weights[b * RB_W + off]);
            float keep = 1.0f - e * w;
            float add  = gt * w;
            float4 wv = __ldg(&wvec4[b * D4 + d4]);
            cur[k].x = cur[k].x * keep + add * wv.x;
            cur[k].y = cur[k].y * keep + add * wv.y;
            cur[k].z = cur[k].z * keep + add * wv.z;
            cur[k].w = cur[k].w * keep + add * wv.w;
        }
    }

#pragma unroll
    for (int k = 0; k < 4; k++) {
        __stcs(&out4[g + k * 256], cur[k]);
    }
}

extern "C" void kernel_launch(void* const* d_in, const int* in_sizes, int n_in,
                              void* d_out, int out_size)
{
    const float4* ring4   = (const float4*)d_in[0];
    const float4* wvec4   = (const float4*)d_in[1];
    const float*  weights = (const float*)d_in[2];
    const float*  erase   = (const float*)d_in[3];
    const float*  wgate   = (const float*)d_in[4];
    const int*    idx     = (const int*)d_in[5];
    float4*       out4    = (float4*)d_out;

    const long long total = (long long)RB_B * RB_M * (RB_D / 4);   // 2^25 float4
    const int threads = 256;
    const int per_block = threads * 4;                              // 1024 float4
    const int blocks = (int)(total / per_block);                    // 32768 (exact)

    ring_update_kernel<<<blocks, threads>>>(ring4, wvec4, weights, erase, wgate, idx, out4);
}

// round 12
// speedup vs baseline: 1.1216x; 1.0020x over previous
#include <cuda_runtime.h>
#include <cuda_bf16.h>

// Problem constants: B=32, M=32768, D=128, R=64, W=129
#define RB_B 32
#define RB_M 32768
#define RB_D 128
#define RB_W 129
#define THREADS 256
#define UNROLL 4
// floats: per thread-access = 8 (256-bit), per iter stride = THREADS*8 = 2048,
// per block = 2048*UNROLL = 8192 floats = 64 rows. Total 2^27 floats.

// out[b,m,:] = ring[b,m,:] unless off=(m-start[b]) mod M < W:
//   w = weights[b,off]; out = ring*(1-erase[b]*w) + write_gate[b]*w*write_vec[b,:]
//
// HBM-bound copy (512MB R + 512MB W compulsory). This round: 256-bit
// LDG.E.256/STG.E.256 (sm_100+ v8.f32) — half the LSU instructions and
// L1tex queue entries per byte vs float4, same front-batched MLP_p1=4.

__device__ __forceinline__ void ldg256cs(const float* p, float* r) {
    asm volatile("ld.global.cs.v8.f32 {%0,%1,%2,%3,%4,%5,%6,%7}, [%8];"
                 : "=f"(r[0]), "=f"(r[1]), "=f"(r[2]), "=f"(r[3]),
                   "=f"(r[4]), "=f"(r[5]), "=f"(r[6]), "=f"(r[7])
                 : "l"(p));
}

__device__ __forceinline__ void stg256cs(float* p, const float* r) {
    asm volatile("st.global.cs.v8.f32 [%0], {%1,%2,%3,%4,%5,%6,%7,%8};"
                 :: "l"(p), "f"(r[0]), "f"(r[1]), "f"(r[2]), "f"(r[3]),
                    "f"(r[4]), "f"(r[5]), "f"(r[6]), "f"(r[7])
                 : "memory");
}

__global__ __launch_bounds__(THREADS) void ring_update_kernel(
    const float* __restrict__ ring,      // B*M*D floats
    const float* __restrict__ wvec,      // B*D floats
    const float* __restrict__ weights,   // B*W
    const float* __restrict__ erase,     // B
    const float* __restrict__ wgate,     // B
    const int*   __restrict__ idx,       // B*W
    float*       __restrict__ out)
{
    // First v8-group base (float index) for this thread.
    int g = blockIdx.x * (THREADS * 8 * UNROLL) + threadIdx.x * 8;

    float r[UNROLL][8];

    // Front-batched independent 256-bit loads: MLP_p1 = 4 (32B each).
#pragma unroll
    for (int k = 0; k < UNROLL; k++) {
        ldg256cs(ring + g + k * (THREADS * 8), r[k]);
    }

    // Block (64 rows) lies fully inside one batch: per-batch M*D = 2^22
    // floats is a multiple of 8192. Scalars hoisted, L1-resident.
    int b      = g >> 22;
    int start  = __ldg(&idx[b * RB_W]);
    float e    = __ldg(&erase[b]);
    float gt   = __ldg(&wgate[b]);

#pragma unroll
    for (int k = 0; k < UNROLL; k++) {
        int v   = g + k * (THREADS * 8);     // group base float index
        int row = v >> 7;                    // b*M + m
        int m   = row & (RB_M - 1);
        int off = (m - start) & (RB_M - 1);

        if (off < RB_W) {
            float w  = __ldg(&weights[b * RB_W + off]);
            float keep = 1.0f - e * w;
            float add  = gt * w;
            const float* wv = wvec + b * RB_D + (v & (RB_D - 1));
#pragma unroll
            for (int j = 0; j < 8; j++) {
                r[k][j] = r[k][j] * keep + add * __ldg(&wv[j]);
            }
        }
    }

#pragma unroll
    for (int k = 0; k < UNROLL; k++) {
        stg256cs(out + g + k * (THREADS * 8), r[k]);
    }
}

extern "C" void kernel_launch(void* const* d_in, const int* in_sizes, int n_in,
                              void* d_out, int out_size)
{
    const float* ring    = (const float*)d_in[0];
    const float* wvec    = (const float*)d_in[1];
    const float* weights = (const float*)d_in[2];
    const float* erase   = (const float*)d_in[3];
    const float* wgate   = (const float*)d_in[4];
    const int*   idx     = (const int*)d_in[5];
    float*       out     = (float*)d_out;

    const long long total = (long long)RB_B * RB_M * RB_D;     // 2^27 floats
    const int per_block = THREADS * 8 * UNROLL;                // 8192 floats
    const int blocks = (int)(total / per_block);               // 16384 (exact)

    ring_update_kernel<<<blocks, THREADS>>>(ring, wvec, weights, erase, wgate, idx, out);
}